// round 8
// baseline (speedup 1.0000x reference)
#include <cuda_runtime.h>
#include <cstdint>

// NodePropagatorSparse: out[b,e,0:256]   = node_states[b, edge_src[e], :]
//                       out[b,e,256:512] = node_states[b, edge_tgt[e], :]
// B=4, N=10000, E=160000, D=256. node_states fp32, indices int32 (JAX x64-off).
//
// R8: batch phasing (blockIdx.y=b, 10.24MB L2-resident gather set per phase)
// + edge-unroll x8 per thread (MLP=8) to push DRAM busy 88% -> ~92%.
// __stcs evict-first streaming stores.

#define B_DIM 4
#define N_DIM 10000
#define E_DIM 160000
#define D_DIM 256
#define D4    (D_DIM / 4)        // 64 float4 per D-row
#define ROW4  (2 * D4)           // 128 float4 per output (b,e) row
#define EDGES_PER_BLOCK 16
#define UNROLL 8

__global__ __launch_bounds__(256, 6)
void node_prop_gather_kernel(const float4* __restrict__ ns4,   // [B, N, D4]
                             const int* __restrict__ src,      // [E] int32
                             const int* __restrict__ tgt,      // [E] int32
                             float4* __restrict__ out4)        // [B, E, ROW4]
{
    const int t    = threadIdx.x;                 // 0..255
    const int b    = blockIdx.y;                  // batch phase
    const int half = (t >> 6) & 1;                // 0 = src half, 1 = tgt half
    const int col  = t & 63;                      // float4 column within D-row
    const int esub = t >> 7;                      // 0..1: edge-within-pair

    const int e0 = blockIdx.x * EDGES_PER_BLOCK + esub;
    const int* iarr = half ? tgt : src;

    const float4* nsb = ns4 + (size_t)b * ((size_t)N_DIM * D4) + col;
    float4* outb = out4 + (size_t)b * ((size_t)E_DIM * ROW4) + half * D4 + col;

    int idx[UNROLL];
#pragma unroll
    for (int u = 0; u < UNROLL; u++)
        idx[u] = iarr[e0 + 2 * u];

    float4 v[UNROLL];
#pragma unroll
    for (int u = 0; u < UNROLL; u++)
        v[u] = nsb[(size_t)idx[u] * D4];

#pragma unroll
    for (int u = 0; u < UNROLL; u++)
        __stcs(&outb[(size_t)(e0 + 2 * u) * ROW4], v[u]);
}

extern "C" void kernel_launch(void* const* d_in, const int* in_sizes, int n_in,
                              void* d_out, int out_size)
{
    const float4* ns4  = (const float4*)d_in[0];
    const int*    src  = (const int*)d_in[1];
    const int*    tgt  = (const int*)d_in[2];
    float4*       out4 = (float4*)d_out;

    dim3 grid(E_DIM / EDGES_PER_BLOCK, B_DIM);   // (10000, 4)
    node_prop_gather_kernel<<<grid, 256>>>(ns4, src, tgt, out4);
}